// round 1
// baseline (speedup 1.0000x reference)
#include <cuda_runtime.h>

// OccupancyPooling: N=8192 agents, 6x6 occupancy grid (cell side 0.5) of other
// agents relative to each agent, then Linear(36 -> 128).
//
// Phase 1 (occ_count_kernel): 67M pair evaluations, per-thread private smem
//   histogram counters, j-range split 8 ways for chip saturation, partial int
//   counts written to __device__ scratch (no atomics, fully rewritten each launch).
// Phase 2 (occ_gemm_kernel): reduce 8 partials, subtract self-pair (cell 21),
//   occ @ W.T + b with W in bank-conflict-free padded smem.

#define N_AGENTS 8192
#define GRID_G   6
#define NCELL    36          // 6*6
#define HIDDEN   128
#define S_CHUNKS 8
#define CHUNK    (N_AGENTS / S_CHUNKS)   // 1024
#define T1       256
#define I_TILES  (N_AGENTS / T1)         // 32
#define SLOTS    37          // 36 cells + 1 dummy slot for out-of-range pairs

#define T2       256
#define ROWS2    16

// Partial histograms: [j-chunk][agent][cell]. 8*8192*36*4 = 9.4 MB.
// Every slot is rewritten on every launch -> deterministic, no zeroing needed.
__device__ int g_part[S_CHUNKS][N_AGENTS][NCELL];

__global__ __launch_bounds__(T1) void occ_count_kernel(const float2* __restrict__ obs) {
    __shared__ float2 sobs[CHUNK];          // 8 KB
    __shared__ int    cnt[T1 * SLOTS];      // 37888 B

    const int tid   = threadIdx.x;
    const int iTile = blockIdx.x;
    const int s     = blockIdx.y;
    const int i     = iTile * T1 + tid;     // agent owned by this thread

    // Stage this block's j-chunk into shared memory (coalesced).
    const float2* src = obs + s * CHUNK;
    for (int k = tid; k < CHUNK; k += T1) sobs[k] = src[k];

    // Zero private counters (stride-37 layout: bank = 5*lane + slot mod 32).
    int* mycnt = &cnt[tid * SLOTS];
    #pragma unroll
    for (int c = 0; c < SLOTS; c++) mycnt[c] = 0;

    const float2 pi = obs[i];
    const float xi = pi.x, yi = pi.y;

    __syncthreads();

    #pragma unroll 8
    for (int j = 0; j < CHUNK; j++) {
        const float2 pj = sobs[j];          // broadcast across warp
        // Exactly matches reference: (xj - xi)/0.5 + 3.0  (/0.5 is exact)
        const float u = fmaf(pj.x - xi, 2.0f, 3.0f);
        const float v = fmaf(pj.y - yi, 2.0f, 3.0f);
        const int iu = __float2int_rd(u);   // floor; negatives -> negative ints
        const int iv = __float2int_rd(v);
        const bool ok = ((unsigned)iu < GRID_G) && ((unsigned)iv < GRID_G);
        const int slot = ok ? (iu * GRID_G + iv) : NCELL;   // dummy slot if OOR
        mycnt[slot]++;
    }

    // Flush this thread's 36 real counters to the partial buffer.
    #pragma unroll
    for (int c = 0; c < NCELL; c++)
        g_part[s][i][c] = mycnt[c];
}

__global__ __launch_bounds__(T2) void occ_gemm_kernel(
    const float* __restrict__ W,   // [HIDDEN, 36] row-major
    const float* __restrict__ b,   // [HIDDEN]
    float* __restrict__ out)       // [N_AGENTS, HIDDEN]
{
    __shared__ float Ws[HIDDEN * 37];       // padded stride 37 -> conflict-free
    __shared__ float occs[ROWS2 * NCELL];

    const int tid   = threadIdx.x;
    const int rbase = blockIdx.x * ROWS2;

    // Load W into padded smem.
    for (int idx = tid; idx < HIDDEN * NCELL; idx += T2) {
        const int h = idx / NCELL, c = idx - h * NCELL;
        Ws[h * 37 + c] = W[idx];
    }

    // Reduce the 8 partials; remove the self pair (always lands in cell 21:
    // rel = (3,3) for j == i; inputs contain no NaNs).
    for (int idx = tid; idx < ROWS2 * NCELL; idx += T2) {
        const int r = idx / NCELL, c = idx - r * NCELL;
        const int i = rbase + r;
        int sum = 0;
        #pragma unroll
        for (int s = 0; s < S_CHUNKS; s++) sum += g_part[s][i][c];
        float f = (float)sum;
        if (c == 21) f -= 1.0f;
        occs[idx] = f;
    }
    __syncthreads();

    const int h  = tid & (HIDDEN - 1);      // lanes -> consecutive h
    const int hy = tid >> 7;                // row-group 0/1
    const float bh = b[h];

    float acc[8];
    #pragma unroll
    for (int k = 0; k < 8; k++) acc[k] = bh;

    #pragma unroll
    for (int c = 0; c < NCELL; c++) {
        const float wc = Ws[h * 37 + c];    // conflict-free (stride 37)
        #pragma unroll
        for (int k = 0; k < 8; k++)
            acc[k] = fmaf(occs[(hy * 8 + k) * NCELL + c], wc, acc[k]);  // broadcast
    }

    #pragma unroll
    for (int k = 0; k < 8; k++)
        out[(rbase + hy * 8 + k) * HIDDEN + h] = acc[k];    // coalesced
}

extern "C" void kernel_launch(void* const* d_in, const int* in_sizes, int n_in,
                              void* d_out, int out_size) {
    const float2* obs = (const float2*)d_in[0];   // [8192, 2] f32
    const float*  W   = (const float*) d_in[1];   // [128, 36] f32
    const float*  b   = (const float*) d_in[2];   // [128] f32
    float* out = (float*)d_out;                   // [8192, 128] f32

    dim3 g1(I_TILES, S_CHUNKS);                   // 32 x 8 = 256 blocks
    occ_count_kernel<<<g1, T1>>>(obs);
    occ_gemm_kernel<<<N_AGENTS / ROWS2, T2>>>(W, b, out);
}

// round 2
// speedup vs baseline: 1.5331x; 1.5331x over previous
#include <cuda_runtime.h>

// OccupancyPooling: N=8192 agents, 6x6 relative occupancy histogram over all
// pairs, then Linear(36 -> 128).
//
// R2 changes vs R1 (92.7us):
//  - counter smem layout [slot][tid]: bank = tid%32, conflict-free for ANY slot
//  - floor via FADD.RM magic constant (full-rate fma pipe) instead of F2I
//    (quarter-rate conversion pipe); bit-exact floors incl. negative/OOR
//  - 32 x 37 = 1184 = 148*8 blocks: perfect SM load balance
//  - u8 partials (counts <= 222 per chunk), 10.9MB, no atomics, deterministic
//  - gemm: 128 blocks x 64 rows, 32 accumulators/thread, W loaded 128x not 512x

#define N_AGENTS 8192
#define GRID_G   6
#define NCELL    36
#define HIDDEN   128
#define S_CHUNKS 37
#define CHUNK    222                    // ceil(8192/37); last chunk = 200
#define T1       256
#define I_TILES  (N_AGENTS / T1)        // 32  -> 32*37 = 1184 = 148*8 blocks
#define SLOTS    37                     // 36 cells + dummy for out-of-range

#define T2       256
#define ROWS2    64                     // rows per gemm block -> 128 blocks

// Partial histograms [j-chunk][cell][agent], u8 (max count per chunk = 222).
// Fully rewritten every launch -> deterministic, no zeroing kernel needed.
__device__ unsigned char g_part[S_CHUNKS][NCELL][N_AGENTS];

__device__ __forceinline__ void count_pair(float px, float py, float xi, float yi,
                                           unsigned* cnt, int tid) {
    // Exactly matches reference fp32 sequence: (xj-xi)/0.5 + 3 == fma(xj-xi,2,3)
    // (the *2 is exact, so fused == separate rounding).
    const float u = fmaf(px - xi, 2.0f, 3.0f);
    const float v = fmaf(py - yi, 2.0f, 3.0f);
    // floor via round-toward-minus-inf add of 2^23: mantissa bits == floor(u)
    // for u in [0, 2^23); negative u gives bits < 0x4B000000 -> iu < 0 ->
    // rejected by the unsigned compare. Full-rate FADD.RM, no F2I.
    const int iu = __float_as_int(__fadd_rd(u, 8388608.0f)) - 0x4B000000;
    const int iv = __float_as_int(__fadd_rd(v, 8388608.0f)) - 0x4B000000;
    const unsigned ok = ((unsigned)iu < 6u) & ((unsigned)iv < 6u);
    const unsigned slot = ok ? (unsigned)(iu * GRID_G + iv) : (unsigned)NCELL;
    cnt[slot * T1 + tid] += 1u;          // bank = tid%32: always conflict-free
}

__global__ __launch_bounds__(T1) void occ_count_kernel(const float2* __restrict__ obs) {
    __shared__ float2   sobs[CHUNK + 2];       // staged j-chunk (~1.8 KB)
    __shared__ unsigned cnt[SLOTS * T1];       // [slot][tid], 37888 B

    const int tid  = threadIdx.x;
    const int i    = blockIdx.x * T1 + tid;    // agent owned by this thread
    const int s    = blockIdx.y;               // j-chunk id
    const int jBeg = s * CHUNK;
    const int jn   = min(CHUNK, N_AGENTS - jBeg);   // 222 or 200 (both even)

    // Stage j-chunk (coalesced).
    for (int k = tid; k < jn; k += T1) sobs[k] = obs[jBeg + k];

    // Zero private counters.
    #pragma unroll
    for (int c = 0; c < SLOTS; c++) cnt[c * T1 + tid] = 0u;

    const float2 pi = obs[i];
    const float xi = pi.x, yi = pi.y;

    __syncthreads();

    // 2 pairs per float4 broadcast load from shared.
    const float4* s4 = (const float4*)sobs;
    const int jn2 = jn >> 1;
    #pragma unroll 4
    for (int jj = 0; jj < jn2; jj++) {
        const float4 p = s4[jj];
        count_pair(p.x, p.y, xi, yi, cnt, tid);
        count_pair(p.z, p.w, xi, yi, cnt, tid);
    }

    // Flush 36 real counters (u8, coalesced over i).
    #pragma unroll
    for (int c = 0; c < NCELL; c++)
        g_part[s][c][i] = (unsigned char)cnt[c * T1 + tid];
}

__global__ __launch_bounds__(T2) void occ_gemm_kernel(
    const float* __restrict__ W,   // [128, 36] row-major
    const float* __restrict__ b,   // [128]
    float* __restrict__ out)       // [8192, 128]
{
    __shared__ float Ws[HIDDEN * 37];          // stride-37 pad: conflict-free
    __shared__ float occs[ROWS2 * NCELL];      // 9216 B

    const int tid   = threadIdx.x;
    const int rbase = blockIdx.x * ROWS2;

    // Load W into padded smem (18 KB, L2-hot after first block).
    for (int idx = tid; idx < HIDDEN * NCELL; idx += T2) {
        const int h = idx / NCELL, c = idx - h * NCELL;
        Ws[h * 37 + c] = W[idx];
    }

    // Reduce 37 u8 partials; subtract the self pair (always cell 21: rel=(3,3)).
    for (int idx = tid; idx < ROWS2 * NCELL; idx += T2) {
        const int c = idx >> 6;                // idx = c*64 + r: coalesced in r
        const int r = idx & 63;
        const int i = rbase + r;
        int sum = 0;
        #pragma unroll
        for (int s = 0; s < S_CHUNKS; s++) sum += (int)g_part[s][c][i];
        float f = (float)sum;
        if (c == 21) f -= 1.0f;
        occs[r * NCELL + c] = f;
    }
    __syncthreads();

    const int h  = tid & (HIDDEN - 1);         // lanes -> consecutive h
    const int hy = tid >> 7;                   // row half 0/1 (uniform per warp)
    const float bh = b[h];

    float acc[32];
    #pragma unroll
    for (int k = 0; k < 32; k++) acc[k] = bh;

    #pragma unroll
    for (int c = 0; c < NCELL; c++) {
        const float wc = Ws[h * 37 + c];       // stride 37: conflict-free
        const float* oc = &occs[(hy * 32) * NCELL + c];
        #pragma unroll
        for (int k = 0; k < 32; k++)
            acc[k] = fmaf(oc[k * NCELL], wc, acc[k]);   // warp-broadcast
    }

    #pragma unroll
    for (int k = 0; k < 32; k++)
        out[(rbase + hy * 32 + k) * HIDDEN + h] = acc[k];   // coalesced
}

extern "C" void kernel_launch(void* const* d_in, const int* in_sizes, int n_in,
                              void* d_out, int out_size) {
    const float2* obs = (const float2*)d_in[0];   // [8192, 2] f32
    const float*  W   = (const float*) d_in[1];   // [128, 36] f32
    const float*  b   = (const float*) d_in[2];   // [128] f32
    float* out = (float*)d_out;                   // [8192, 128] f32

    dim3 g1(I_TILES, S_CHUNKS);                   // 32 x 37 = 1184 = 148*8
    occ_count_kernel<<<g1, T1>>>(obs);
    occ_gemm_kernel<<<N_AGENTS / ROWS2, T2>>>(W, b, out);
}

// round 3
// speedup vs baseline: 1.7167x; 1.1197x over previous
#include <cuda_runtime.h>

// OccupancyPooling: N=8192 agents, 6x6 relative occupancy histogram over all
// pairs (67M), then Linear(36 -> 128).
//
// R3 vs R2 (60.4us):
//  - predicated increment: out-of-range pairs (~50%!) no longer RMW a shared
//    dummy slot (smem has no store-forwarding -> same-address LDS/STS chains)
//  - 32 x 23 = 736 blocks = 148 SMs x 5 resident (smem-limited): single wave,
//    no wave quantization
//  - dedicated coalesced reduce kernel (u8 partials -> f32 occ_t[36][8192])
//  - gemm: 512 blocks x 16 rows, 8 acc/thread (~48 regs), reads occ_t directly

#define N_AGENTS 8192
#define GRID_G   6
#define NCELL    36
#define HIDDEN   128
#define S_CHUNKS 23
#define CHUNK    358                    // 23*358 = 8234 >= 8192; last jn = 316 (even)
#define T1       256
#define I_TILES  (N_AGENTS / T1)        // 32 -> 32*23 = 736 = 148*5 - 4 blocks
#define SLOTS    37

#define TR       256                    // reduce kernel threads
#define T2       256
#define ROWS2    16                     // -> 512 gemm blocks

// Partial histograms [chunk][cell][agent] u8 (max count/chunk << 255 for this
// data). Fully rewritten every launch -> deterministic, no zeroing.
__device__ unsigned char g_part[S_CHUNKS][NCELL][N_AGENTS];
// Reduced occupancy, cell-major for coalescing in both reduce and gemm.
__device__ float g_occ[NCELL][N_AGENTS];

__device__ __forceinline__ void count_pair(float px, float py, float xi, float yi,
                                           unsigned* cnt, int tid) {
    // Bit-exact vs reference: (xj-xi)/0.5 + 3 == fma(xj-xi, 2, 3) (x2 exact).
    const float u = fmaf(px - xi, 2.0f, 3.0f);
    const float v = fmaf(py - yi, 2.0f, 3.0f);
    // floor via round-toward--inf add of 2^23 (full-rate FADD.RM, no F2I):
    // mantissa == floor(u) for u in [0,2^23); u<0 -> iu<0 -> unsigned reject.
    const int iu = __float_as_int(__fadd_rd(u, 8388608.0f)) - 0x4B000000;
    const int iv = __float_as_int(__fadd_rd(v, 8388608.0f)) - 0x4B000000;
    if (((unsigned)iu < 6u) & ((unsigned)iv < 6u)) {
        cnt[(iu * GRID_G + iv) * T1 + tid] += 1u;   // bank = tid%32: conflict-free
    }
}

__global__ __launch_bounds__(T1, 5) void occ_count_kernel(const float2* __restrict__ obs) {
    __shared__ float2   sobs[CHUNK];           // 2864 B
    __shared__ unsigned cnt[SLOTS * T1];       // [slot][tid], 37888 B

    const int tid  = threadIdx.x;
    const int i    = blockIdx.x * T1 + tid;    // agent owned by this thread
    const int s    = blockIdx.y;               // j-chunk
    const int jBeg = s * CHUNK;
    const int jn   = min(CHUNK, N_AGENTS - jBeg);   // 358 or 316, both even

    for (int k = tid; k < jn; k += T1) sobs[k] = obs[jBeg + k];

    #pragma unroll
    for (int c = 0; c < SLOTS; c++) cnt[c * T1 + tid] = 0u;

    const float2 pi = obs[i];
    const float xi = pi.x, yi = pi.y;

    __syncthreads();

    const float4* s4 = (const float4*)sobs;    // 2 pairs per broadcast load
    const int jn2 = jn >> 1;
    #pragma unroll 4
    for (int jj = 0; jj < jn2; jj++) {
        const float4 p = s4[jj];
        count_pair(p.x, p.y, xi, yi, cnt, tid);
        count_pair(p.z, p.w, xi, yi, cnt, tid);
    }

    #pragma unroll
    for (int c = 0; c < NCELL; c++)
        g_part[s][c][i] = (unsigned char)cnt[c * T1 + tid];   // coalesced u8
}

// Reduce 23 u8 partials -> f32; subtract the self pair (always cell 21:
// rel=(3,3) for j==i, no NaNs in input). c is uniform per block.
__global__ __launch_bounds__(TR) void occ_reduce_kernel() {
    const int gid = blockIdx.x * TR + threadIdx.x;   // over 36*8192
    const int c = gid >> 13;                         // /8192 (uniform in block)
    const int i = gid & (N_AGENTS - 1);
    int sum = 0;
    #pragma unroll
    for (int s = 0; s < S_CHUNKS; s++) sum += (int)g_part[s][c][i];
    float f = (float)sum;
    if (c == 21) f -= 1.0f;
    g_occ[c][i] = f;
}

__global__ __launch_bounds__(T2) void occ_gemm_kernel(
    const float* __restrict__ W,   // [128, 36] row-major
    const float* __restrict__ b,   // [128]
    float* __restrict__ out)       // [8192, 128]
{
    __shared__ float Ws[HIDDEN * 37];          // stride-37 pad: conflict-free
    __shared__ float occs[ROWS2 * NCELL];

    const int tid   = threadIdx.x;
    const int rbase = blockIdx.x * ROWS2;

    for (int idx = tid; idx < HIDDEN * NCELL; idx += T2) {
        const int h = idx / NCELL, c = idx - h * NCELL;
        Ws[h * 37 + c] = W[idx];
    }
    for (int idx = tid; idx < ROWS2 * NCELL; idx += T2) {
        const int c = idx >> 4;                // 16 consecutive rows per c
        const int r = idx & (ROWS2 - 1);
        occs[r * NCELL + c] = g_occ[c][rbase + r];
    }
    __syncthreads();

    const int h  = tid & (HIDDEN - 1);         // lanes -> consecutive h
    const int hy = tid >> 7;                   // row half (uniform per warp)
    const float bh = b[h];

    float acc[8];
    #pragma unroll
    for (int k = 0; k < 8; k++) acc[k] = bh;

    #pragma unroll
    for (int c = 0; c < NCELL; c++) {
        const float wc = Ws[h * 37 + c];       // conflict-free
        const float* oc = &occs[(hy * 8) * NCELL + c];
        #pragma unroll
        for (int k = 0; k < 8; k++)
            acc[k] = fmaf(oc[k * NCELL], wc, acc[k]);   // warp-broadcast
    }

    #pragma unroll
    for (int k = 0; k < 8; k++)
        out[(rbase + hy * 8 + k) * HIDDEN + h] = acc[k];    // coalesced
}

extern "C" void kernel_launch(void* const* d_in, const int* in_sizes, int n_in,
                              void* d_out, int out_size) {
    const float2* obs = (const float2*)d_in[0];   // [8192, 2] f32
    const float*  W   = (const float*) d_in[1];   // [128, 36] f32
    const float*  b   = (const float*) d_in[2];   // [128] f32
    float* out = (float*)d_out;                   // [8192, 128] f32

    dim3 g1(I_TILES, S_CHUNKS);                   // 736 blocks: one full wave
    occ_count_kernel<<<g1, T1>>>(obs);
    occ_reduce_kernel<<<(NCELL * N_AGENTS) / TR, TR>>>();
    occ_gemm_kernel<<<N_AGENTS / ROWS2, T2>>>(W, b, out);
}

// round 4
// speedup vs baseline: 1.8505x; 1.0780x over previous
#include <cuda_runtime.h>
#include <cstdint>

// OccupancyPooling: N=8192, 6x6 relative occupancy over all 67M pairs, then
// Linear(36 -> 128).
//
// R4 vs R3 (54.0us, count=41.6us issue-bound at ~17 inst/pair):
//  - packed f32x2 (FADD2/FFMA2/FADD2.RM): (x,y) computed in 3 fma-pipe ops
//    instead of 6; bit-exact rounding vs reference preserved
//  - index trick: (bu*6+bv)*256 == slot*256 (mod 2^32) since 7*0x4B000000*256
//    wraps to 0 -> 2 IMADs, no bias subtraction
//  - everything else (predicated increment, [slot][tid] conflict-free u32
//    counters, 736-block single wave, reduce+gemm split) kept from R3

#define N_AGENTS 8192
#define GRID_G   6
#define NCELL    36
#define HIDDEN   128
#define S_CHUNKS 23
#define CHUNK    358                    // last jn = 316 (both even)
#define T1       256
#define I_TILES  (N_AGENTS / T1)        // 32 -> 736 blocks = 148*5 - 4
#define SLOTS    37

#define TR       256
#define T2       256
#define ROWS2    16                     // 512 gemm blocks

__device__ unsigned char g_part[S_CHUNKS][NCELL][N_AGENTS];
__device__ float g_occ[NCELL][N_AGENTS];

__device__ __forceinline__ unsigned long long pack2(float lo, float hi) {
    unsigned long long r;
    asm("mov.b64 %0, {%1, %2};" : "=l"(r) : "f"(lo), "f"(hi));
    return r;
}

// One pair: packed (x,y) pipeline. Bit-exact vs reference:
//   d  = rn(pj - pi)                  (negation exact; packed FADD2)
//   r  = rn(d*2 + 3)                  (d*2 exact -> single rounding, same as
//                                      separate /0.5 then +3; packed FFMA2)
//   m  = rd(r + 2^23)                 (magic floor; bits = 0x4B000000+floor(r)
//                                      for r in [0,2^23), bits < 0x4B000000
//                                      for r < 0; packed FADD2.RM)
__device__ __forceinline__ void count_pair(unsigned long long xy,
                                           unsigned long long negxy,
                                           unsigned long long two2,
                                           unsigned long long three2,
                                           unsigned long long magic2,
                                           unsigned* __restrict__ cnt_t) {
    unsigned long long d, r, m;
    asm("add.rn.f32x2 %0, %1, %2;" : "=l"(d) : "l"(xy), "l"(negxy));
    asm("fma.rn.f32x2 %0, %1, %2, %3;" : "=l"(r) : "l"(d), "l"(two2), "l"(three2));
    asm("add.rm.f32x2 %0, %1, %2;" : "=l"(m) : "l"(r), "l"(magic2));
    unsigned bu, bv;
    asm("mov.b64 {%0, %1}, %2;" : "=r"(bu), "=r"(bv) : "l"(m));
    // (bu*6+bv)*256 == (iu*6+iv)*256 (mod 2^32): the 7*0x4B000000 bias times
    // 256 is a multiple of 2^32. Valid lanes index [0, 36*256); others are
    // never dereferenced (predicated off).
    const unsigned idx = (bu * 6u + bv) * 256u;
    if ((bu - 0x4B000000u) < 6u && (bv - 0x4B000000u) < 6u)
        cnt_t[idx] += 1u;               // bank = tid%32: conflict-free
}

__global__ __launch_bounds__(T1, 5) void occ_count_kernel(const float2* __restrict__ obs) {
    __shared__ __align__(16) float2 sobs[CHUNK];
    __shared__ unsigned cnt[SLOTS * T1];       // [slot][tid], 37888 B

    const int tid  = threadIdx.x;
    const int i    = blockIdx.x * T1 + tid;
    const int s    = blockIdx.y;
    const int jBeg = s * CHUNK;
    const int jn   = min(CHUNK, N_AGENTS - jBeg);

    for (int k = tid; k < jn; k += T1) sobs[k] = obs[jBeg + k];

    #pragma unroll
    for (int c = 0; c < SLOTS; c++) cnt[c * T1 + tid] = 0u;

    const float2 pi = obs[i];
    const unsigned long long negxy  = pack2(-pi.x, -pi.y);
    const unsigned long long two2   = pack2(2.0f, 2.0f);
    const unsigned long long three2 = pack2(3.0f, 3.0f);
    const unsigned long long magic2 = pack2(8388608.0f, 8388608.0f);
    unsigned* cnt_t = cnt + tid;

    __syncthreads();

    const float4* s4 = (const float4*)sobs;    // 2 pairs per LDS.128
    const int jn2 = jn >> 1;
    #pragma unroll 4
    for (int jj = 0; jj < jn2; jj++) {
        const float4 p = s4[jj];
        unsigned long long xy0, xy1;
        asm("mov.b64 %0, {%1, %2};" : "=l"(xy0) : "f"(p.x), "f"(p.y));
        asm("mov.b64 %0, {%1, %2};" : "=l"(xy1) : "f"(p.z), "f"(p.w));
        count_pair(xy0, negxy, two2, three2, magic2, cnt_t);
        count_pair(xy1, negxy, two2, three2, magic2, cnt_t);
    }

    #pragma unroll
    for (int c = 0; c < NCELL; c++)
        g_part[s][c][i] = (unsigned char)cnt[c * T1 + tid];   // coalesced u8
}

// Reduce 23 u8 partials -> f32; subtract the self pair (always cell 21).
__global__ __launch_bounds__(TR) void occ_reduce_kernel() {
    const int gid = blockIdx.x * TR + threadIdx.x;
    const int c = gid >> 13;                   // uniform per block
    const int i = gid & (N_AGENTS - 1);
    int sum = 0;
    #pragma unroll
    for (int s = 0; s < S_CHUNKS; s++) sum += (int)g_part[s][c][i];
    float f = (float)sum;
    if (c == 21) f -= 1.0f;
    g_occ[c][i] = f;
}

__global__ __launch_bounds__(T2) void occ_gemm_kernel(
    const float* __restrict__ W,   // [128, 36] row-major
    const float* __restrict__ b,   // [128]
    float* __restrict__ out)       // [8192, 128]
{
    __shared__ float Ws[HIDDEN * 37];
    __shared__ float occs[ROWS2 * NCELL];

    const int tid   = threadIdx.x;
    const int rbase = blockIdx.x * ROWS2;

    for (int idx = tid; idx < HIDDEN * NCELL; idx += T2) {
        const int h = idx / NCELL, c = idx - h * NCELL;
        Ws[h * 37 + c] = W[idx];
    }
    for (int idx = tid; idx < ROWS2 * NCELL; idx += T2) {
        const int c = idx >> 4;
        const int r = idx & (ROWS2 - 1);
        occs[r * NCELL + c] = g_occ[c][rbase + r];
    }
    __syncthreads();

    const int h  = tid & (HIDDEN - 1);
    const int hy = tid >> 7;
    const float bh = b[h];

    float acc[8];
    #pragma unroll
    for (int k = 0; k < 8; k++) acc[k] = bh;

    #pragma unroll
    for (int c = 0; c < NCELL; c++) {
        const float wc = Ws[h * 37 + c];
        const float* oc = &occs[(hy * 8) * NCELL + c];
        #pragma unroll
        for (int k = 0; k < 8; k++)
            acc[k] = fmaf(oc[k * NCELL], wc, acc[k]);
    }

    #pragma unroll
    for (int k = 0; k < 8; k++)
        out[(rbase + hy * 8 + k) * HIDDEN + h] = acc[k];
}

extern "C" void kernel_launch(void* const* d_in, const int* in_sizes, int n_in,
                              void* d_out, int out_size) {
    const float2* obs = (const float2*)d_in[0];
    const float*  W   = (const float*) d_in[1];
    const float*  b   = (const float*) d_in[2];
    float* out = (float*)d_out;

    dim3 g1(I_TILES, S_CHUNKS);
    occ_count_kernel<<<g1, T1>>>(obs);
    occ_reduce_kernel<<<(NCELL * N_AGENTS) / TR, TR>>>();
    occ_gemm_kernel<<<N_AGENTS / ROWS2, T2>>>(W, b, out);
}

// round 5
// speedup vs baseline: 2.0351x; 1.0998x over previous
#include <cuda_runtime.h>
#include <cstdint>

// OccupancyPooling: N=8192, 6x6 relative occupancy over all 67M pairs, then
// Linear(36 -> 128).
//
// R5 vs R4 (50.1us = 34.8 count + 15.3 reduce/gemm/launch):
//  - count reshaped T1=128, CHUNK=128, S=64: 19456B smem/block -> 12 resident
//    blocks = 48 warps/SM (exact 228KB fit), up from 40; regs capped at 42
//  - bias-cancel at byte scale 512: (7*0x4B000000*512) mod 2^32 == 0, so the
//    slot byte offset needs just 2 IMADs, no bias subtract
//  - reduce fused into gemm: phase A sums 64 u8 partials with unsigned dp4a
//    byte extraction (counts <= 128, so UNSIGNED dp4a is required), phase B
//    is the broadcast GEMM; one fewer kernel node, no g_occ roundtrip

#define N_AGENTS 8192
#define NCELL    36
#define HIDDEN   128
#define T1       128
#define CHUNK    128                    // 64 chunks * 128 = 8192 exact
#define S_CHUNKS 64
#define I_TILES  (N_AGENTS / T1)        // 64 -> grid 64x64 = 4096 blocks

#define T2       256
#define ROWS2    32                     // 256 gemm blocks

// Partial histograms [chunk][cell][agent] u8 (max count per chunk = 128).
// Fully rewritten every launch -> deterministic, no zeroing.
__device__ unsigned char g_part[S_CHUNKS][NCELL][N_AGENTS];

__device__ __forceinline__ unsigned long long pack2(float lo, float hi) {
    unsigned long long r;
    asm("mov.b64 %0, {%1, %2};" : "=l"(r) : "f"(lo), "f"(hi));
    return r;
}

// One pair, bit-exact vs reference:
//   d = rn(pj - pi)            packed FADD2 (negation exact, rn symmetric)
//   r = rn(d*2 + 3)            packed FFMA2 (d*2 exact -> same as /0.5 then +3)
//   m = rd(r + 2^23)           packed FADD2.RM magic floor:
//                              bits = 0x4B000000 + floor(r) for r in [0,2^23),
//                              bits < 0x4B000000 for r < 0
__device__ __forceinline__ void count_pair(unsigned long long xy,
                                           unsigned long long negxy,
                                           unsigned long long two2,
                                           unsigned long long three2,
                                           unsigned long long magic2,
                                           char* __restrict__ cnt_t) {
    unsigned long long d, r, m;
    asm("add.rn.f32x2 %0, %1, %2;" : "=l"(d) : "l"(xy), "l"(negxy));
    asm("fma.rn.f32x2 %0, %1, %2, %3;" : "=l"(r) : "l"(d), "l"(two2), "l"(three2));
    asm("add.rm.f32x2 %0, %1, %2;" : "=l"(m) : "l"(r), "l"(magic2));
    unsigned bu, bv;
    asm("mov.b64 {%0, %1}, %2;" : "=r"(bu), "=r"(bv) : "l"(m));
    // byte offset: (bu*6+bv)*512 wraps (mod 2^32) to slot*512 exactly
    // (7*0x4B000000*512 == 26*2^32). Only dereferenced when in range.
    const unsigned offb = (bu * 6u + bv) * 512u;
    if ((bu - 0x4B000000u) < 6u && (bv - 0x4B000000u) < 6u)
        *(unsigned*)(cnt_t + offb) += 1u;   // [slot][tid]: bank=tid%32, no conflicts
}

__global__ __launch_bounds__(T1, 12) void occ_count_kernel(const float2* __restrict__ obs) {
    __shared__ __align__(16) float2 sobs[CHUNK];   // 1024 B
    __shared__ unsigned cnt[NCELL * T1];           // [slot][tid], 18432 B

    const int tid = threadIdx.x;
    const int i   = blockIdx.x * T1 + tid;
    const int s   = blockIdx.y;

    sobs[tid] = obs[s * CHUNK + tid];              // one coalesced load

    #pragma unroll
    for (int c = 0; c < NCELL; c++) cnt[c * T1 + tid] = 0u;

    const float2 pi = obs[i];
    const unsigned long long negxy  = pack2(-pi.x, -pi.y);
    const unsigned long long two2   = pack2(2.0f, 2.0f);
    const unsigned long long three2 = pack2(3.0f, 3.0f);
    const unsigned long long magic2 = pack2(8388608.0f, 8388608.0f);
    char* cnt_t = (char*)(cnt + tid);

    __syncthreads();

    const float4* s4 = (const float4*)sobs;        // 2 pairs per LDS.128
    #pragma unroll 8
    for (int jj = 0; jj < CHUNK / 2; jj++) {
        const float4 p = s4[jj];
        unsigned long long xy0, xy1;
        asm("mov.b64 %0, {%1, %2};" : "=l"(xy0) : "f"(p.x), "f"(p.y));
        asm("mov.b64 %0, {%1, %2};" : "=l"(xy1) : "f"(p.z), "f"(p.w));
        count_pair(xy0, negxy, two2, three2, magic2, cnt_t);
        count_pair(xy1, negxy, two2, three2, magic2, cnt_t);
    }

    #pragma unroll
    for (int c = 0; c < NCELL; c++)
        g_part[s][c][i] = (unsigned char)cnt[c * T1 + tid];   // coalesced u8
}

// Fused reduce + GEMM.
// Phase A: sum 64 u8 partials into occs[32][36] via unsigned dp4a byte picks;
//          subtract the self pair (always cell 21: rel=(3,3) for j==i).
// Phase B: out[r,:] = occs[r,:] @ W.T + b, W in stride-37 (conflict-free) smem.
__global__ __launch_bounds__(T2) void occ_gemm_kernel(
    const float* __restrict__ W,   // [128, 36] row-major
    const float* __restrict__ b,   // [128]
    float* __restrict__ out)       // [8192, 128]
{
    __shared__ float Ws[HIDDEN * 37];          // 18944 B
    __shared__ float occs[ROWS2 * NCELL];      // 4608 B

    const int tid   = threadIdx.x;
    const int rbase = blockIdx.x * ROWS2;

    for (int idx = tid; idx < HIDDEN * NCELL; idx += T2) {
        const int h = idx / NCELL, c = idx - h * NCELL;
        Ws[h * 37 + c] = W[idx];
    }

    // Phase A: 288 (c, quad) work items; quad = 4 consecutive rows (one uint).
    for (int id = tid; id < NCELL * (ROWS2 / 4); id += T2) {
        const int c = id >> 3;                 // /8 quads
        const int q = id & 7;
        unsigned a0 = 0, a1 = 0, a2 = 0, a3 = 0;
        #pragma unroll
        for (int s = 0; s < S_CHUNKS; s++) {
            const unsigned w = *(const unsigned*)&g_part[s][c][rbase + q * 4];
            a0 = __dp4a(w, 0x00000001u, a0);   // byte 0 (unsigned: counts can be 128)
            a1 = __dp4a(w, 0x00000100u, a1);   // byte 1
            a2 = __dp4a(w, 0x00010000u, a2);   // byte 2
            a3 = __dp4a(w, 0x01000000u, a3);   // byte 3
        }
        const float self = (c == 21) ? 1.0f : 0.0f;
        occs[(q * 4 + 0) * NCELL + c] = (float)a0 - self;
        occs[(q * 4 + 1) * NCELL + c] = (float)a1 - self;
        occs[(q * 4 + 2) * NCELL + c] = (float)a2 - self;
        occs[(q * 4 + 3) * NCELL + c] = (float)a3 - self;
    }
    __syncthreads();

    // Phase B
    const int h  = tid & (HIDDEN - 1);         // lanes -> consecutive h
    const int hy = tid >> 7;                   // row half (uniform per warp)
    const float bh = b[h];

    float acc[16];
    #pragma unroll
    for (int k = 0; k < 16; k++) acc[k] = bh;

    #pragma unroll
    for (int c = 0; c < NCELL; c++) {
        const float wc = Ws[h * 37 + c];       // stride 37: conflict-free
        const float* oc = &occs[(hy * 16) * NCELL + c];
        #pragma unroll
        for (int k = 0; k < 16; k++)
            acc[k] = fmaf(oc[k * NCELL], wc, acc[k]);   // warp-broadcast
    }

    #pragma unroll
    for (int k = 0; k < 16; k++)
        out[(rbase + hy * 16 + k) * HIDDEN + h] = acc[k];   // coalesced
}

extern "C" void kernel_launch(void* const* d_in, const int* in_sizes, int n_in,
                              void* d_out, int out_size) {
    const float2* obs = (const float2*)d_in[0];   // [8192, 2] f32
    const float*  W   = (const float*) d_in[1];   // [128, 36] f32
    const float*  b   = (const float*) d_in[2];   // [128] f32
    float* out = (float*)d_out;                   // [8192, 128] f32

    dim3 g1(I_TILES, S_CHUNKS);                   // 64 x 64 = 4096 blocks
    occ_count_kernel<<<g1, T1>>>(obs);
    occ_gemm_kernel<<<N_AGENTS / ROWS2, T2>>>(W, b, out);
}